// round 5
// baseline (speedup 1.0000x reference)
#include <cuda_runtime.h>
#include <cuda_bf16.h>
#include <cstdint>

#define NN 100000
#define NE 1600000
#define HDIM 128

// ---------------- static device scratch ----------------
__device__ float4 g_bufA[(size_t)NN * 32];   // N x 128 floats (agg output)
__device__ float4 g_bufB[(size_t)NN * 32];   // pre-BN linear output / head hidden
__device__ float4 g_bufC[(size_t)NN * 32];   // layer outputs

__device__ int g_counts[NN];
__device__ int g_scanTmp[NN];
__device__ int g_partials[128];
__device__ int g_rowptr[NN + 1];
__device__ int g_cursor[NN];
__device__ int g_srcSorted[NE];
__device__ int g_is64;                        // edge_index dtype flag (device-detected)

__device__ float g_Ssum[HDIM];
__device__ float g_Ssq[HDIM];
__device__ float g_scale[HDIM];
__device__ float g_shift[HDIM];

template<int B> __device__ __forceinline__ float* bufsel();
template<> __device__ __forceinline__ float* bufsel<0>() { return (float*)g_bufA; }
template<> __device__ __forceinline__ float* bufsel<1>() { return (float*)g_bufB; }
template<> __device__ __forceinline__ float* bufsel<2>() { return (float*)g_bufC; }

// Read logical element `pos` of edge_index, handling int32 vs int64 storage.
__device__ __forceinline__ int edge_at(const int* __restrict__ ei, long long pos, int is64) {
    return is64 ? ei[2 * pos] : ei[(size_t)pos];   // little-endian low word
}

// ---------------- dtype detector ----------------
// Sample odd 32-bit words within the first NE logical elements (always in
// bounds for both dtypes). int64 data: high words of values < 2^31 are all 0.
// int32 data: these words are node indices, mostly nonzero.
__global__ void k_detect(const int* __restrict__ ei) {
    __shared__ int nz;
    if (threadIdx.x == 0) nz = 0;
    __syncthreads();
    long long p = (long long)threadIdx.x * (NE / 256);
    if (ei[2 * p + 1] != 0) atomicAdd(&nz, 1);
    __syncthreads();
    if (threadIdx.x == 0) g_is64 = (nz == 0) ? 1 : 0;
}

// ---------------- CSR build (all indices clamped) ----------------
__global__ void k_zero_counts() {
    int i = blockIdx.x * blockDim.x + threadIdx.x;
    if (i < NN) g_counts[i] = 0;
}

__global__ void k_hist(const int* __restrict__ ei) {
    int e = blockIdx.x * blockDim.x + threadIdx.x;
    if (e < NE) {
        int is64 = g_is64;
        unsigned d = (unsigned)edge_at(ei, (long long)NE + e, is64);
        if (d < NN) atomicAdd(&g_counts[d], 1);
    }
}

__global__ void k_scan1() {
    __shared__ int s[1024];
    int idx = blockIdx.x * 1024 + threadIdx.x;
    int v = (idx < NN) ? g_counts[idx] : 0;
    s[threadIdx.x] = v;
    __syncthreads();
    for (int off = 1; off < 1024; off <<= 1) {
        int t = 0;
        if (threadIdx.x >= off) t = s[threadIdx.x - off];
        __syncthreads();
        s[threadIdx.x] += t;
        __syncthreads();
    }
    if (idx < NN) g_scanTmp[idx] = s[threadIdx.x];
    if (threadIdx.x == 1023) g_partials[blockIdx.x] = s[1023];
}

__global__ void k_scan2(int nblocks) {
    __shared__ int s[128];
    int t = threadIdx.x;
    int v = (t < nblocks) ? g_partials[t] : 0;
    s[t] = v;
    __syncthreads();
    for (int off = 1; off < 128; off <<= 1) {
        int tv = 0;
        if (t >= off) tv = s[t - off];
        __syncthreads();
        s[t] += tv;
        __syncthreads();
    }
    g_partials[t] = s[t];
    if (t == 0) g_rowptr[0] = 0;
}

__global__ void k_scan3() {
    int idx = blockIdx.x * 1024 + threadIdx.x;
    if (idx < NN) {
        int off = (blockIdx.x > 0) ? g_partials[blockIdx.x - 1] : 0;
        int incl = g_scanTmp[idx] + off;
        int excl = incl - g_counts[idx];
        g_rowptr[idx] = excl;
        g_cursor[idx] = excl;
        if (idx == NN - 1) g_rowptr[NN] = incl;
    }
}

__global__ void k_scatter(const int* __restrict__ ei) {
    int e = blockIdx.x * blockDim.x + threadIdx.x;
    if (e < NE) {
        int is64 = g_is64;
        int s = edge_at(ei, e, is64);
        unsigned d = (unsigned)edge_at(ei, (long long)NE + e, is64);
        if (d < NN) {
            int pos = atomicAdd(&g_cursor[d], 1);
            g_srcSorted[pos] = s;
        }
    }
}

// ---------------- aggregation: warp per node, gather ----------------
// out[i] = (1+eps)*x[i] + sum_{e: dst=i} x[src[e]]
__global__ void k_agg64(const float* __restrict__ x, const float* __restrict__ epsp) {
    int warp = (blockIdx.x * blockDim.x + threadIdx.x) >> 5;
    int lane = threadIdx.x & 31;
    if (warp >= NN) return;
    int lo = g_rowptr[warp], hi = g_rowptr[warp + 1];
    float eps1 = 1.0f + *epsp;
    const float2* xb = (const float2*)x;  // 32 float2 per row
    float2 self = xb[(size_t)warp * 32 + lane];
    float2 acc;
    acc.x = self.x * eps1; acc.y = self.y * eps1;
    for (int e = lo; e < hi; ++e) {
        int s = g_srcSorted[e];
        if ((unsigned)s < NN) {
            float2 v = xb[(size_t)s * 32 + lane];
            acc.x += v.x; acc.y += v.y;
        }
    }
    ((float2*)g_bufA)[(size_t)warp * 32 + lane] = acc;
}

__global__ void k_agg128(const float* __restrict__ epsp) {
    int warp = (blockIdx.x * blockDim.x + threadIdx.x) >> 5;
    int lane = threadIdx.x & 31;
    if (warp >= NN) return;
    int lo = g_rowptr[warp], hi = g_rowptr[warp + 1];
    float eps1 = 1.0f + *epsp;
    const float4* xb = g_bufC;  // 32 float4 per row
    float4 self = xb[(size_t)warp * 32 + lane];
    float4 acc;
    acc.x = self.x * eps1; acc.y = self.y * eps1;
    acc.z = self.z * eps1; acc.w = self.w * eps1;
    for (int e = lo; e < hi; ++e) {
        int s = g_srcSorted[e];
        if ((unsigned)s < NN) {
            float4 v = xb[(size_t)s * 32 + lane];
            acc.x += v.x; acc.y += v.y; acc.z += v.z; acc.w += v.w;
        }
    }
    g_bufA[(size_t)warp * 32 + lane] = acc;
}

// ---------------- BN helpers ----------------
__global__ void k_zero_stats() {
    int j = threadIdx.x;
    if (j < HDIM) { g_Ssum[j] = 0.f; g_Ssq[j] = 0.f; }
}

__global__ void k_bn_finalize(const float* __restrict__ gamma, const float* __restrict__ beta) {
    int j = threadIdx.x;
    if (j < HDIM) {
        float mu = g_Ssum[j] / (float)NN;
        float var = g_Ssq[j] / (float)NN - mu * mu;
        var = fmaxf(var, 0.f);
        float sc = gamma[j] * rsqrtf(var + 1e-5f);
        g_scale[j] = sc;
        g_shift[j] = beta[j] - mu * sc;
    }
}

// ---------------- GEMM: [NN x K] @ [K x 128] + bias ----------------
template<int K, int SRC, int DST, bool IN_BN, bool OUT_RELU, bool STATS>
__global__ void __launch_bounds__(256)
k_gemm(const float* __restrict__ W, const float* __restrict__ bias) {
    const float* A = bufsel<SRC>();
    float* out = bufsel<DST>();

    __shared__ __align__(16) float As[8][128];
    __shared__ __align__(16) float Ws[8][128];
    __shared__ __align__(16) float red[16][128];

    int tid = threadIdx.x;
    int tx = tid & 15;      // 8 output cols each
    int ty = tid >> 4;      // 8 output rows each
    int rowBase = blockIdx.x * 128;

    float acc[8][8];
#pragma unroll
    for (int i = 0; i < 8; i++)
#pragma unroll
        for (int j = 0; j < 8; j++) acc[i][j] = 0.f;

    int lrow = tid >> 1;
    int lhalf = tid & 1;
    int wrow = tid >> 5;
    int wcol = (tid & 31) * 4;

    for (int kk = 0; kk < K; kk += 8) {
        int gr = rowBase + lrow;
        float4 a4 = make_float4(0.f, 0.f, 0.f, 0.f);
        if (gr < NN)
            a4 = *(const float4*)(A + (size_t)gr * K + kk + lhalf * 4);
        if (IN_BN) {
            int kb = kk + lhalf * 4;
            a4.x = fmaxf(a4.x * g_scale[kb + 0] + g_shift[kb + 0], 0.f);
            a4.y = fmaxf(a4.y * g_scale[kb + 1] + g_shift[kb + 1], 0.f);
            a4.z = fmaxf(a4.z * g_scale[kb + 2] + g_shift[kb + 2], 0.f);
            a4.w = fmaxf(a4.w * g_scale[kb + 3] + g_shift[kb + 3], 0.f);
        }
        As[lhalf * 4 + 0][lrow] = a4.x;
        As[lhalf * 4 + 1][lrow] = a4.y;
        As[lhalf * 4 + 2][lrow] = a4.z;
        As[lhalf * 4 + 3][lrow] = a4.w;
        *(float4*)&Ws[wrow][wcol] = *(const float4*)(W + (size_t)(kk + wrow) * 128 + wcol);
        __syncthreads();

#pragma unroll
        for (int k = 0; k < 8; k++) {
            float aF[8], bF[8];
#pragma unroll
            for (int i = 0; i < 8; i++) aF[i] = As[k][ty * 8 + i];
#pragma unroll
            for (int j = 0; j < 8; j++) bF[j] = Ws[k][tx * 8 + j];
#pragma unroll
            for (int i = 0; i < 8; i++)
#pragma unroll
                for (int j = 0; j < 8; j++) acc[i][j] += aF[i] * bF[j];
        }
        __syncthreads();
    }

    float cS[8], cQ[8];
#pragma unroll
    for (int j = 0; j < 8; j++) { cS[j] = 0.f; cQ[j] = 0.f; }

#pragma unroll
    for (int i = 0; i < 8; i++) {
        int gr = rowBase + ty * 8 + i;
        if (gr < NN) {
            float vv[8];
#pragma unroll
            for (int j = 0; j < 8; j++) {
                int c = tx * 8 + j;
                float v = acc[i][j] + bias[c];
                if (OUT_RELU) v = fmaxf(v, 0.f);
                vv[j] = v;
                if (STATS) { cS[j] += v; cQ[j] += v * v; }
            }
            *(float4*)(out + (size_t)gr * 128 + tx * 8 + 0) =
                make_float4(vv[0], vv[1], vv[2], vv[3]);
            *(float4*)(out + (size_t)gr * 128 + tx * 8 + 4) =
                make_float4(vv[4], vv[5], vv[6], vv[7]);
        }
    }

    if (STATS) {
        __syncthreads();
#pragma unroll
        for (int j = 0; j < 8; j++) red[ty][tx * 8 + j] = cS[j];
        __syncthreads();
        if (ty == 0) {
#pragma unroll
            for (int j = 0; j < 8; j++) {
                int c = tx * 8 + j;
                float s = 0.f;
#pragma unroll
                for (int t = 0; t < 16; t++) s += red[t][c];
                atomicAdd(&g_Ssum[c], s);
            }
        }
        __syncthreads();
#pragma unroll
        for (int j = 0; j < 8; j++) red[ty][tx * 8 + j] = cQ[j];
        __syncthreads();
        if (ty == 0) {
#pragma unroll
            for (int j = 0; j < 8; j++) {
                int c = tx * 8 + j;
                float s = 0.f;
#pragma unroll
                for (int t = 0; t < 16; t++) s += red[t][c];
                atomicAdd(&g_Ssq[c], s);
            }
        }
    }
}

// ---------------- head final: g_bufB [N x 128] @ [128 x 2] + bias ----------------
__global__ void k_head2(const float* __restrict__ hwb, const float* __restrict__ hbb,
                        float* __restrict__ out) {
    __shared__ __align__(16) float sw[256];
    int tid = threadIdx.x;
    sw[tid] = hwb[tid];
    __syncthreads();
    int warp = (blockIdx.x * blockDim.x + tid) >> 5;
    int lane = tid & 31;
    if (warp >= NN) return;
    float4 h4 = g_bufB[(size_t)warp * 32 + lane];
    int k0 = lane * 4;
    float p0 = h4.x * sw[2 * k0 + 0] + h4.y * sw[2 * k0 + 2] +
               h4.z * sw[2 * k0 + 4] + h4.w * sw[2 * k0 + 6];
    float p1 = h4.x * sw[2 * k0 + 1] + h4.y * sw[2 * k0 + 3] +
               h4.z * sw[2 * k0 + 5] + h4.w * sw[2 * k0 + 7];
#pragma unroll
    for (int o = 16; o > 0; o >>= 1) {
        p0 += __shfl_down_sync(0xffffffffu, p0, o);
        p1 += __shfl_down_sync(0xffffffffu, p1, o);
    }
    if (lane == 0) {
        out[(size_t)warp * 2 + 0] = p0 + hbb[0];
        out[(size_t)warp * 2 + 1] = p1 + hbb[1];
    }
}

// ---------------- launch ----------------
extern "C" void kernel_launch(void* const* d_in, const int* in_sizes, int n_in,
                              void* d_out, int out_size) {
    const float* x = (const float*)d_in[0];
    const int* ei = (const int*)d_in[1];   // int32 OR int64 storage; detected on device

    const float* wa[3]; const float* ba[3]; const float* gm[3]; const float* be[3];
    const float* wb[3]; const float* bb[3]; const float* ep[3];
    for (int l = 0; l < 3; l++) {
        int b = 2 + 7 * l;
        wa[l] = (const float*)d_in[b + 0];
        ba[l] = (const float*)d_in[b + 1];
        gm[l] = (const float*)d_in[b + 2];
        be[l] = (const float*)d_in[b + 3];
        wb[l] = (const float*)d_in[b + 4];
        bb[l] = (const float*)d_in[b + 5];
        ep[l] = (const float*)d_in[b + 6];
    }
    const float* hwa = (const float*)d_in[23];
    const float* hba = (const float*)d_in[24];
    const float* hwb = (const float*)d_in[25];
    const float* hbb = (const float*)d_in[26];
    float* out = (float*)d_out;

    const int NB1 = (NN + 1023) / 1024;      // 98
    const int GB = (NN + 127) / 128;          // 782
    const int AGGB = (NN + 7) / 8;            // 12500

    // edge dtype detection + CSR build (reused by all 3 layers)
    k_detect<<<1, 256>>>(ei);
    k_zero_counts<<<(NN + 255) / 256, 256>>>();
    k_hist<<<(NE + 255) / 256, 256>>>(ei);
    k_scan1<<<NB1, 1024>>>();
    k_scan2<<<1, 128>>>(NB1);
    k_scan3<<<NB1, 1024>>>();
    k_scatter<<<(NE + 255) / 256, 256>>>(ei);

    // ---- layer 0 (din = 64): x -> bufA -> bufB -> bufC ----
    k_agg64<<<AGGB, 256>>>(x, ep[0]);
    k_zero_stats<<<1, 128>>>();
    k_gemm<64, 0, 1, false, false, true><<<GB, 256>>>(wa[0], ba[0]);
    k_bn_finalize<<<1, 128>>>(gm[0], be[0]);
    k_gemm<128, 1, 2, true, true, false><<<GB, 256>>>(wb[0], bb[0]);

    // ---- layers 1,2 (din = 128): bufC -> bufA -> bufB -> bufC ----
    for (int l = 1; l < 3; l++) {
        k_agg128<<<AGGB, 256>>>(ep[l]);
        k_zero_stats<<<1, 128>>>();
        k_gemm<128, 0, 1, false, false, true><<<GB, 256>>>(wa[l], ba[l]);
        k_bn_finalize<<<1, 128>>>(gm[l], be[l]);
        k_gemm<128, 1, 2, true, true, false><<<GB, 256>>>(wb[l], bb[l]);
    }

    // ---- head: bufC -> bufB -> out ----
    k_gemm<128, 2, 1, false, true, false><<<GB, 256>>>(hwa, hba);
    k_head2<<<AGGB, 256>>>(hwb, hbb, out);
}

// round 6
// speedup vs baseline: 1.3444x; 1.3444x over previous
#include <cuda_runtime.h>
#include <cuda_bf16.h>
#include <cstdint>

#define NN 100000
#define NE 1600000
#define HDIM 128

// ---------------- static device scratch ----------------
__device__ float4 g_bufA[(size_t)NN * 32];   // N x 128 floats (agg output)
__device__ float4 g_bufB[(size_t)NN * 32];   // pre-BN linear output / head hidden
__device__ float4 g_bufC[(size_t)NN * 32];   // layer outputs

__device__ int g_counts[NN];
__device__ int g_scanTmp[NN];
__device__ int g_partials[128];
__device__ int g_rowptr[NN + 1];
__device__ int g_cursor[NN];
__device__ int g_srcSorted[NE];
__device__ int g_is64;                        // edge_index dtype flag

__device__ float g_Ssum[HDIM];
__device__ float g_Ssq[HDIM];
__device__ float g_scale[HDIM];
__device__ float g_shift[HDIM];

// Pre-split weights, transposed to [n][k] bf16 (hi / lo), 16B-aligned storage.
__device__ uint4 g_WtHi[128 * 128 * 2 / 16];
__device__ uint4 g_WtLo[128 * 128 * 2 / 16];

template<int B> __device__ __forceinline__ float* bufsel();
template<> __device__ __forceinline__ float* bufsel<0>() { return (float*)g_bufA; }
template<> __device__ __forceinline__ float* bufsel<1>() { return (float*)g_bufB; }
template<> __device__ __forceinline__ float* bufsel<2>() { return (float*)g_bufC; }

__device__ __forceinline__ int edge_at(const int* __restrict__ ei, long long pos, int is64) {
    return is64 ? ei[2 * pos] : ei[(size_t)pos];
}

// ---------------- dtype detector ----------------
__global__ void k_detect(const int* __restrict__ ei) {
    __shared__ int nz;
    if (threadIdx.x == 0) nz = 0;
    __syncthreads();
    long long p = (long long)threadIdx.x * (NE / 256);
    if (ei[2 * p + 1] != 0) atomicAdd(&nz, 1);
    __syncthreads();
    if (threadIdx.x == 0) g_is64 = (nz == 0) ? 1 : 0;
}

// ---------------- CSR build ----------------
__global__ void k_zero_counts() {
    int i = blockIdx.x * blockDim.x + threadIdx.x;
    if (i < NN) g_counts[i] = 0;
}

__global__ void k_hist(const int* __restrict__ ei) {
    int e = blockIdx.x * blockDim.x + threadIdx.x;
    if (e < NE) {
        int is64 = g_is64;
        unsigned d = (unsigned)edge_at(ei, (long long)NE + e, is64);
        if (d < NN) atomicAdd(&g_counts[d], 1);
    }
}

__global__ void k_scan1() {
    __shared__ int s[1024];
    int idx = blockIdx.x * 1024 + threadIdx.x;
    int v = (idx < NN) ? g_counts[idx] : 0;
    s[threadIdx.x] = v;
    __syncthreads();
    for (int off = 1; off < 1024; off <<= 1) {
        int t = 0;
        if (threadIdx.x >= off) t = s[threadIdx.x - off];
        __syncthreads();
        s[threadIdx.x] += t;
        __syncthreads();
    }
    if (idx < NN) g_scanTmp[idx] = s[threadIdx.x];
    if (threadIdx.x == 1023) g_partials[blockIdx.x] = s[1023];
}

__global__ void k_scan2(int nblocks) {
    __shared__ int s[128];
    int t = threadIdx.x;
    int v = (t < nblocks) ? g_partials[t] : 0;
    s[t] = v;
    __syncthreads();
    for (int off = 1; off < 128; off <<= 1) {
        int tv = 0;
        if (t >= off) tv = s[t - off];
        __syncthreads();
        s[t] += tv;
        __syncthreads();
    }
    g_partials[t] = s[t];
    if (t == 0) g_rowptr[0] = 0;
}

__global__ void k_scan3() {
    int idx = blockIdx.x * 1024 + threadIdx.x;
    if (idx < NN) {
        int off = (blockIdx.x > 0) ? g_partials[blockIdx.x - 1] : 0;
        int incl = g_scanTmp[idx] + off;
        int excl = incl - g_counts[idx];
        g_rowptr[idx] = excl;
        g_cursor[idx] = excl;
        if (idx == NN - 1) g_rowptr[NN] = incl;
    }
}

__global__ void k_scatter(const int* __restrict__ ei) {
    int e = blockIdx.x * blockDim.x + threadIdx.x;
    if (e < NE) {
        int is64 = g_is64;
        int s = edge_at(ei, e, is64);
        unsigned d = (unsigned)edge_at(ei, (long long)NE + e, is64);
        if (d < NN) {
            int pos = atomicAdd(&g_cursor[d], 1);
            g_srcSorted[pos] = s;
        }
    }
}

// ---------------- aggregation: warp per node, gather ----------------
__global__ void k_agg64(const float* __restrict__ x, const float* __restrict__ epsp) {
    int warp = (blockIdx.x * blockDim.x + threadIdx.x) >> 5;
    int lane = threadIdx.x & 31;
    if (warp >= NN) return;
    int lo = g_rowptr[warp], hi = g_rowptr[warp + 1];
    float eps1 = 1.0f + *epsp;
    const float2* xb = (const float2*)x;
    float2 self = xb[(size_t)warp * 32 + lane];
    float2 acc;
    acc.x = self.x * eps1; acc.y = self.y * eps1;
    for (int e = lo; e < hi; ++e) {
        int s = g_srcSorted[e];
        if ((unsigned)s < NN) {
            float2 v = xb[(size_t)s * 32 + lane];
            acc.x += v.x; acc.y += v.y;
        }
    }
    ((float2*)g_bufA)[(size_t)warp * 32 + lane] = acc;
}

__global__ void k_agg128(const float* __restrict__ epsp) {
    int warp = (blockIdx.x * blockDim.x + threadIdx.x) >> 5;
    int lane = threadIdx.x & 31;
    if (warp >= NN) return;
    int lo = g_rowptr[warp], hi = g_rowptr[warp + 1];
    float eps1 = 1.0f + *epsp;
    const float4* xb = g_bufC;
    float4 self = xb[(size_t)warp * 32 + lane];
    float4 acc;
    acc.x = self.x * eps1; acc.y = self.y * eps1;
    acc.z = self.z * eps1; acc.w = self.w * eps1;
    for (int e = lo; e < hi; ++e) {
        int s = g_srcSorted[e];
        if ((unsigned)s < NN) {
            float4 v = xb[(size_t)s * 32 + lane];
            acc.x += v.x; acc.y += v.y; acc.z += v.z; acc.w += v.w;
        }
    }
    g_bufA[(size_t)warp * 32 + lane] = acc;
}

// ---------------- BN helpers ----------------
__global__ void k_zero_stats() {
    int j = threadIdx.x;
    if (j < HDIM) { g_Ssum[j] = 0.f; g_Ssq[j] = 0.f; }
}

__global__ void k_bn_finalize(const float* __restrict__ gamma, const float* __restrict__ beta) {
    int j = threadIdx.x;
    if (j < HDIM) {
        float mu = g_Ssum[j] / (float)NN;
        float var = g_Ssq[j] / (float)NN - mu * mu;
        var = fmaxf(var, 0.f);
        float sc = gamma[j] * rsqrtf(var + 1e-5f);
        g_scale[j] = sc;
        g_shift[j] = beta[j] - mu * sc;
    }
}

// ---------------- weight pre-split: W[K][128] fp32 -> Wt hi/lo [128][K] bf16 ----------------
__global__ void k_prepW(const float* __restrict__ W, int K) {
    int idx = blockIdx.x * 256 + threadIdx.x;
    if (idx < K * 128) {
        int k = idx >> 7, n = idx & 127;
        float v = W[idx];
        __nv_bfloat16 hi = __float2bfloat16(v);
        __nv_bfloat16 lo = __float2bfloat16(v - __bfloat162float(hi));
        ((__nv_bfloat16*)g_WtHi)[n * K + k] = hi;
        ((__nv_bfloat16*)g_WtLo)[n * K + k] = lo;
    }
}

// ---------------- split-bf16 tensor-core GEMM ----------------
__device__ __forceinline__ void mma_bf16(float* d, const uint32_t* a, const uint32_t* b) {
    asm volatile(
        "mma.sync.aligned.m16n8k16.row.col.f32.bf16.bf16.f32 "
        "{%0,%1,%2,%3}, {%4,%5,%6,%7}, {%8,%9}, {%0,%1,%2,%3};\n"
        : "+f"(d[0]), "+f"(d[1]), "+f"(d[2]), "+f"(d[3])
        : "r"(a[0]), "r"(a[1]), "r"(a[2]), "r"(a[3]), "r"(b[0]), "r"(b[1]));
}

// C[NN x 128] = A[NN x K] @ W[K x 128] (+bias, optional BN-in / relu-out / stats)
// A split into hi/lo bf16 on the fly; W pre-split in g_WtHi/g_WtLo ([n][k]).
template<int K, int SRC, int DST, bool IN_BN, bool OUT_RELU, bool STATS>
__global__ void __launch_bounds__(256)
k_gemm_mma(const float* __restrict__ bias) {
    const float* A = bufsel<SRC>();
    float* out = bufsel<DST>();
    const __nv_bfloat16* pWhi = (const __nv_bfloat16*)g_WtHi;
    const __nv_bfloat16* pWlo = (const __nv_bfloat16*)g_WtLo;

    __shared__ __align__(16) __nv_bfloat16 sAhi[128 * 16];
    __shared__ __align__(16) __nv_bfloat16 sAlo[128 * 16];
    __shared__ __align__(16) __nv_bfloat16 sBhi[128 * 16];
    __shared__ __align__(16) __nv_bfloat16 sBlo[128 * 16];
    __shared__ float sSum[128], sSq[128];

    const int tid = threadIdx.x;
    const int lane = tid & 31;
    const int warp = tid >> 5;
    const int wm = warp & 3;        // row group: rows wm*32..+31
    const int wn = warp >> 2;       // col group: cols wn*64..+63
    const int qr = lane >> 2;       // 0..7
    const int qc = lane & 3;        // 0..3
    const int rowBase = blockIdx.x * 128;

    if (STATS && tid < 128) { sSum[tid] = 0.f; sSq[tid] = 0.f; }

    float acc[2][8][4];
#pragma unroll
    for (int m = 0; m < 2; m++)
#pragma unroll
        for (int n = 0; n < 8; n++)
#pragma unroll
            for (int j = 0; j < 4; j++) acc[m][n][j] = 0.f;

    for (int kk = 0; kk < K; kk += 16) {
        // ---- stage A tile 128x16, fp32 -> (hi,lo) bf16 ----
#pragma unroll
        for (int it = 0; it < 2; it++) {
            int f = it * 256 + tid;         // 0..511 float4 slots
            int row = f >> 2;
            int c4 = (f & 3) << 2;
            int gr = rowBase + row;
            float4 v = make_float4(0.f, 0.f, 0.f, 0.f);
            if (gr < NN) v = *(const float4*)(A + (size_t)gr * K + kk + c4);
            float vals[4] = {v.x, v.y, v.z, v.w};
#pragma unroll
            for (int j = 0; j < 4; j++) {
                float val = vals[j];
                if (IN_BN) {
                    int kb = kk + c4 + j;
                    val = fmaxf(val * g_scale[kb] + g_shift[kb], 0.f);
                }
                __nv_bfloat16 hi = __float2bfloat16(val);
                __nv_bfloat16 lo = __float2bfloat16(val - __bfloat162float(hi));
                sAhi[row * 16 + c4 + j] = hi;
                sAlo[row * 16 + c4 + j] = lo;
            }
        }
        // ---- stage W tile [128 n][16 k] from pre-split globals ----
        {
            int n = tid >> 1, half = tid & 1;
            *(uint4*)(sBhi + n * 16 + half * 8) =
                *(const uint4*)(pWhi + (size_t)n * K + kk + half * 8);
            *(uint4*)(sBlo + n * 16 + half * 8) =
                *(const uint4*)(pWlo + (size_t)n * K + kk + half * 8);
        }
        __syncthreads();

        const uint32_t* a32h = (const uint32_t*)sAhi;   // [row][8] k-pairs
        const uint32_t* a32l = (const uint32_t*)sAlo;
        const uint32_t* b32h = (const uint32_t*)sBhi;   // [n][8] k-pairs
        const uint32_t* b32l = (const uint32_t*)sBlo;

        uint32_t bh[8][2], bl[8][2];
#pragma unroll
        for (int n = 0; n < 8; n++) {
            int nrow = wn * 64 + n * 8 + qr;
            bh[n][0] = b32h[nrow * 8 + qc];
            bh[n][1] = b32h[nrow * 8 + 4 + qc];
            bl[n][0] = b32l[nrow * 8 + qc];
            bl[n][1] = b32l[nrow * 8 + 4 + qc];
        }
#pragma unroll
        for (int m = 0; m < 2; m++) {
            int r = wm * 32 + m * 16 + qr;
            uint32_t ah[4], al[4];
            ah[0] = a32h[r * 8 + qc];
            ah[1] = a32h[(r + 8) * 8 + qc];
            ah[2] = a32h[r * 8 + 4 + qc];
            ah[3] = a32h[(r + 8) * 8 + 4 + qc];
            al[0] = a32l[r * 8 + qc];
            al[1] = a32l[(r + 8) * 8 + qc];
            al[2] = a32l[r * 8 + 4 + qc];
            al[3] = a32l[(r + 8) * 8 + 4 + qc];
#pragma unroll
            for (int n = 0; n < 8; n++) {
                mma_bf16(acc[m][n], ah, bh[n]);
                mma_bf16(acc[m][n], ah, bl[n]);
                mma_bf16(acc[m][n], al, bh[n]);
            }
        }
        __syncthreads();
    }

    // ---- epilogue ----
    float cS[16], cQ[16];
    if (STATS) {
#pragma unroll
        for (int j = 0; j < 16; j++) { cS[j] = 0.f; cQ[j] = 0.f; }
    }

#pragma unroll
    for (int m = 0; m < 2; m++) {
        int r = rowBase + wm * 32 + m * 16 + qr;
#pragma unroll
        for (int n = 0; n < 8; n++) {
            int c = wn * 64 + n * 8 + qc * 2;
            float b0 = bias[c], b1 = bias[c + 1];
            float v0 = acc[m][n][0] + b0, v1 = acc[m][n][1] + b1;
            float v2 = acc[m][n][2] + b0, v3 = acc[m][n][3] + b1;
            if (OUT_RELU) {
                v0 = fmaxf(v0, 0.f); v1 = fmaxf(v1, 0.f);
                v2 = fmaxf(v2, 0.f); v3 = fmaxf(v3, 0.f);
            }
            if (r < NN) {
                *(float2*)(out + (size_t)r * 128 + c) = make_float2(v0, v1);
                if (STATS) {
                    cS[n * 2] += v0; cS[n * 2 + 1] += v1;
                    cQ[n * 2] += v0 * v0; cQ[n * 2 + 1] += v1 * v1;
                }
            }
            if (r + 8 < NN) {
                *(float2*)(out + (size_t)(r + 8) * 128 + c) = make_float2(v2, v3);
                if (STATS) {
                    cS[n * 2] += v2; cS[n * 2 + 1] += v3;
                    cQ[n * 2] += v2 * v2; cQ[n * 2 + 1] += v3 * v3;
                }
            }
        }
    }

    if (STATS) {
#pragma unroll
        for (int n = 0; n < 8; n++) {
            int c = wn * 64 + n * 8 + qc * 2;
            atomicAdd(&sSum[c], cS[n * 2]);
            atomicAdd(&sSum[c + 1], cS[n * 2 + 1]);
            atomicAdd(&sSq[c], cQ[n * 2]);
            atomicAdd(&sSq[c + 1], cQ[n * 2 + 1]);
        }
        __syncthreads();
        if (tid < 128) {
            atomicAdd(&g_Ssum[tid], sSum[tid]);
            atomicAdd(&g_Ssq[tid], sSq[tid]);
        }
    }
}

// ---------------- head final: g_bufB [N x 128] @ [128 x 2] + bias ----------------
__global__ void k_head2(const float* __restrict__ hwb, const float* __restrict__ hbb,
                        float* __restrict__ out) {
    __shared__ __align__(16) float sw[256];
    int tid = threadIdx.x;
    sw[tid] = hwb[tid];
    __syncthreads();
    int warp = (blockIdx.x * blockDim.x + tid) >> 5;
    int lane = tid & 31;
    if (warp >= NN) return;
    float4 h4 = g_bufB[(size_t)warp * 32 + lane];
    int k0 = lane * 4;
    float p0 = h4.x * sw[2 * k0 + 0] + h4.y * sw[2 * k0 + 2] +
               h4.z * sw[2 * k0 + 4] + h4.w * sw[2 * k0 + 6];
    float p1 = h4.x * sw[2 * k0 + 1] + h4.y * sw[2 * k0 + 3] +
               h4.z * sw[2 * k0 + 5] + h4.w * sw[2 * k0 + 7];
#pragma unroll
    for (int o = 16; o > 0; o >>= 1) {
        p0 += __shfl_down_sync(0xffffffffu, p0, o);
        p1 += __shfl_down_sync(0xffffffffu, p1, o);
    }
    if (lane == 0) {
        out[(size_t)warp * 2 + 0] = p0 + hbb[0];
        out[(size_t)warp * 2 + 1] = p1 + hbb[1];
    }
}

// ---------------- launch ----------------
extern "C" void kernel_launch(void* const* d_in, const int* in_sizes, int n_in,
                              void* d_out, int out_size) {
    const float* x = (const float*)d_in[0];
    const int* ei = (const int*)d_in[1];

    const float* wa[3]; const float* ba[3]; const float* gm[3]; const float* be[3];
    const float* wb[3]; const float* bb[3]; const float* ep[3];
    for (int l = 0; l < 3; l++) {
        int b = 2 + 7 * l;
        wa[l] = (const float*)d_in[b + 0];
        ba[l] = (const float*)d_in[b + 1];
        gm[l] = (const float*)d_in[b + 2];
        be[l] = (const float*)d_in[b + 3];
        wb[l] = (const float*)d_in[b + 4];
        bb[l] = (const float*)d_in[b + 5];
        ep[l] = (const float*)d_in[b + 6];
    }
    const float* hwa = (const float*)d_in[23];
    const float* hba = (const float*)d_in[24];
    const float* hwb = (const float*)d_in[25];
    const float* hbb = (const float*)d_in[26];
    float* out = (float*)d_out;

    const int NB1 = (NN + 1023) / 1024;      // 98
    const int GB = (NN + 127) / 128;          // 782
    const int AGGB = (NN + 7) / 8;            // 12500
    const int PW64 = (64 * 128 + 255) / 256;  // 32
    const int PW128 = (128 * 128 + 255) / 256;// 64

    // edge dtype detection + CSR build (reused by all 3 layers)
    k_detect<<<1, 256>>>(ei);
    k_zero_counts<<<(NN + 255) / 256, 256>>>();
    k_hist<<<(NE + 255) / 256, 256>>>(ei);
    k_scan1<<<NB1, 1024>>>();
    k_scan2<<<1, 128>>>(NB1);
    k_scan3<<<NB1, 1024>>>();
    k_scatter<<<(NE + 255) / 256, 256>>>(ei);

    // ---- layer 0 (din = 64): x -> bufA -> bufB -> bufC ----
    k_agg64<<<AGGB, 256>>>(x, ep[0]);
    k_zero_stats<<<1, 128>>>();
    k_prepW<<<PW64, 256>>>(wa[0], 64);
    k_gemm_mma<64, 0, 1, false, false, true><<<GB, 256>>>(ba[0]);
    k_bn_finalize<<<1, 128>>>(gm[0], be[0]);
    k_prepW<<<PW128, 256>>>(wb[0], 128);
    k_gemm_mma<128, 1, 2, true, true, false><<<GB, 256>>>(bb[0]);

    // ---- layers 1,2 (din = 128): bufC -> bufA -> bufB -> bufC ----
    for (int l = 1; l < 3; l++) {
        k_agg128<<<AGGB, 256>>>(ep[l]);
        k_zero_stats<<<1, 128>>>();
        k_prepW<<<PW128, 256>>>(wa[l], 128);
        k_gemm_mma<128, 0, 1, false, false, true><<<GB, 256>>>(ba[l]);
        k_bn_finalize<<<1, 128>>>(gm[l], be[l]);
        k_prepW<<<PW128, 256>>>(wb[l], 128);
        k_gemm_mma<128, 1, 2, true, true, false><<<GB, 256>>>(bb[l]);
    }

    // ---- head: bufC -> bufB -> out ----
    k_prepW<<<PW128, 256>>>(hwa, 128);
    k_gemm_mma<128, 2, 1, false, true, false><<<GB, 256>>>(hba);
    k_head2<<<AGGB, 256>>>(hwb, hbb, out);
}